// round 14
// baseline (speedup 1.0000x reference)
#include <cuda_runtime.h>
#include <cuda_fp16.h>
#include <cstdint>
#include <math.h>

#define Bsz 128
#define Tsz 256
#define Isz 512
#define Hsz 1024
#define Mpre (Bsz*Tsz)
#define BM 128
#define BN 64

__device__ float  g_P[5][Tsz][Bsz][Hsz];
__device__ __half g_HS16[(size_t)Mpre*Hsz];
__device__ float  g_hlast[Bsz*Hsz];
__device__ __half g_h2[2][Bsz*Hsz];
__device__ float  g_c[Bsz*Hsz];
__device__ int    g_flag[Bsz*8];
__device__ __half g_x16[(size_t)Mpre*Isz];
__device__ __half g_xd16[(size_t)Mpre*Isz];
__device__ __half g_w16[5][Hsz*Isz];
__device__ __half g_wro16[Hsz*Isz];
__device__ __half g_who16[(size_t)Hsz*Hsz];

__device__ __forceinline__ void mma16(float c[4], const unsigned a[4], unsigned b0, unsigned b1){
    asm volatile("mma.sync.aligned.m16n8k16.row.col.f32.f16.f16.f32 "
        "{%0,%1,%2,%3},{%4,%5,%6,%7},{%8,%9},{%0,%1,%2,%3};"
        : "+f"(c[0]),"+f"(c[1]),"+f"(c[2]),"+f"(c[3])
        : "r"(a[0]),"r"(a[1]),"r"(a[2]),"r"(a[3]),"r"(b0),"r"(b1));
}
__device__ __forceinline__ float tanh_fast(float x){
    float r; asm("tanh.approx.f32 %0, %1;" : "=f"(r) : "f"(x)); return r;
}
__device__ __forceinline__ float sig_fast(float x){
    return 0.5f + 0.5f * tanh_fast(0.5f * x);
}
__device__ __forceinline__ int ld_acq(const int* p){
    int v; asm volatile("ld.global.acquire.gpu.b32 %0, [%1];" : "=r"(v) : "l"(p) : "memory");
    return v;
}
__device__ __forceinline__ void st_release_flag(int* p, int v){
    int old;
    asm volatile("atom.release.gpu.global.exch.b32 %0, [%1], %2;"
                 : "=r"(old) : "l"(p), "r"(v) : "memory");
}
__device__ __forceinline__ void cpasync16(unsigned dst, const void* src){
    asm volatile("cp.async.cg.shared.global [%0], [%1], 16;" :: "r"(dst), "l"(src));
}
#define CP_COMMIT() asm volatile("cp.async.commit_group;" ::: "memory")

// ---- one-shot fp32 -> fp16 conversion of GEMM operands ----------------------
__global__ void cvt_all(const float* __restrict__ x, const float* __restrict__ xd,
    const float* __restrict__ Wii, const float* __restrict__ Wif,
    const float* __restrict__ Wig, const float* __restrict__ Wio,
    const float* __restrict__ Wid, const float* __restrict__ Wro,
    const float* __restrict__ Who)
{
    size_t i = (size_t)blockIdx.x*256 + threadIdx.x;
    if (i < (size_t)Mpre*Isz) {
        g_x16[i]  = __float2half_rn(x[i]);
        g_xd16[i] = __float2half_rn(xd[i]);
    }
    if (i < (size_t)Hsz*Isz) {
        g_w16[0][i] = __float2half_rn(Wii[i]);
        g_w16[1][i] = __float2half_rn(Wif[i]);
        g_w16[2][i] = __float2half_rn(Wig[i]);
        g_w16[3][i] = __float2half_rn(Wio[i]);
        g_w16[4][i] = __float2half_rn(Wid[i]);
        g_wro16[i]  = __float2half_rn(Wro[i]);
    }
    if (i < (size_t)Hsz*Hsz) g_who16[i] = __float2half_rn(Who[i]);
}

// ---- fp16 GEMM panel --------------------------------------------------------
__device__ __forceinline__ void gemm16_panel(
    const __half* __restrict__ A, int lda,
    const __half* __restrict__ B, int ldb,
    int K, int tid, unsigned smb, const unsigned* __restrict__ smw,
    float (&cacc)[2][4][4])
{
    const int lane = tid & 31, wid = tid >> 5;
    const int wm = wid & 3, wn = wid >> 2;
    const int gid = lane >> 2, tig = lane & 3;
    const int ra = tid >> 1, qa = (tid & 1) * 2;
    const int rb = tid >> 2, qb = tid & 3;
    const int nIter = K >> 5;

    {
        unsigned dA = smb + (unsigned)(ra*40 + qa*8)*2;
        const __half* sa = A + (size_t)ra*lda + qa*8;
        cpasync16(dA, sa); cpasync16(dA + 16, sa + 8);
        unsigned dB = smb + 10240u + (unsigned)(rb*40 + qb*8)*2;
        cpasync16(dB, B + (size_t)rb*ldb + qb*8);
        CP_COMMIT();
    }
    for (int it = 0; it < nIter; it++) {
        if (it + 1 < nIter) {
            const int k0 = (it + 1) << 5;
            const unsigned bo = (unsigned)((it + 1) & 1) * 15360u;
            unsigned dA = smb + bo + (unsigned)(ra*40 + qa*8)*2;
            const __half* sa = A + (size_t)ra*lda + k0 + qa*8;
            cpasync16(dA, sa); cpasync16(dA + 16, sa + 8);
            unsigned dB = smb + bo + 10240u + (unsigned)(rb*40 + qb*8)*2;
            cpasync16(dB, B + (size_t)rb*ldb + k0 + qb*8);
        }
        CP_COMMIT();
        asm volatile("cp.async.wait_group 1;" ::: "memory");
        __syncthreads();

        const unsigned* wA = smw + (it & 1)*3840;
        const unsigned* wB = wA + 2560;
        #pragma unroll
        for (int kk = 0; kk < 2; kk++) {
            unsigned a[2][4];
            #pragma unroll
            for (int mt = 0; mt < 2; mt++) {
                int base = (wm*32 + mt*16 + gid)*20 + kk*8 + tig;
                a[mt][0] = wA[base];       a[mt][1] = wA[base + 160];
                a[mt][2] = wA[base + 4];   a[mt][3] = wA[base + 164];
            }
            #pragma unroll
            for (int nt = 0; nt < 4; nt++) {
                int wb = (wn*32 + nt*8 + gid)*20 + kk*8 + tig;
                unsigned b0 = wB[wb], b1 = wB[wb + 4];
                mma16(cacc[0][nt], a[0], b0, b1);
                mma16(cacc[1][nt], a[1], b0, b1);
            }
        }
        __syncthreads();
    }
}

// ---- phase A ------------------------------------------------------------------
__global__ __launch_bounds__(256)
void gemm_pre16(const float* __restrict__ b0, const float* __restrict__ b1,
                const float* __restrict__ b2, const float* __restrict__ b3,
                const float* __restrict__ b4)
{
    __shared__ __half st[15360];
    const unsigned smb = (unsigned)__cvta_generic_to_shared(st);
    const unsigned* smw = reinterpret_cast<const unsigned*>(st);
    const int gate = blockIdx.z;
    const int m0 = blockIdx.y * BM;
    const int n0 = blockIdx.x * BN;
    const int tid = threadIdx.x;
    const __half* A  = ((gate == 4) ? g_xd16 : g_x16) + (size_t)m0*Isz;
    const __half* Bp = g_w16[gate] + (size_t)n0*Isz;
    const float* bias = gate==0?b0 : gate==1?b1 : gate==2?b2 : gate==3?b3 : b4;

    float cacc[2][4][4];
    #pragma unroll
    for (int i=0;i<2;i++) for (int j=0;j<4;j++) for (int k=0;k<4;k++) cacc[i][j][k]=0.f;

    gemm16_panel(A, Isz, Bp, Isz, Isz, tid, smb, smw, cacc);

    const int lane = tid & 31, wid = tid >> 5;
    const int wm = wid & 3, wn = wid >> 2;
    const int gid = lane >> 2, tig = lane & 3;
    #pragma unroll
    for (int mt=0; mt<2; mt++)
        #pragma unroll
        for (int nt=0; nt<4; nt++) {
            int row = m0 + wm*32 + mt*16 + gid;
            int b = row >> 8, tt = row & 255;
            int col = n0 + wn*32 + nt*8 + 2*tig;
            float bv0 = bias[col], bv1 = bias[col+1];
            g_P[gate][tt  ][b][col  ] = cacc[mt][nt][0] + bv0;
            g_P[gate][tt  ][b][col+1] = cacc[mt][nt][1] + bv1;
            g_P[gate][tt+8][b][col  ] = cacc[mt][nt][2] + bv0;
            g_P[gate][tt+8][b][col+1] = cacc[mt][nt][3] + bv1;
        }
}

// ---- phase C ------------------------------------------------------------------
__global__ __launch_bounds__(256)
void gemm_out16(const float* __restrict__ Wrb, float* __restrict__ y)
{
    __shared__ __half st[15360];
    const unsigned smb = (unsigned)__cvta_generic_to_shared(st);
    const unsigned* smw = reinterpret_cast<const unsigned*>(st);
    const int m0 = blockIdx.y * BM;
    const int n0 = blockIdx.x * BN;
    const int tid = threadIdx.x;

    float cacc[2][4][4];
    #pragma unroll
    for (int i=0;i<2;i++) for (int j=0;j<4;j++) for (int k=0;k<4;k++) cacc[i][j][k]=0.f;

    gemm16_panel(g_x16  + (size_t)m0*Isz, Isz, g_wro16 + (size_t)n0*Isz, Isz, Isz, tid, smb, smw, cacc);
    gemm16_panel(g_HS16 + (size_t)m0*Hsz, Hsz, g_who16 + (size_t)n0*Hsz, Hsz, Hsz, tid, smb, smw, cacc);

    const int lane = tid & 31, wid = tid >> 5;
    const int wm = wid & 3, wn = wid >> 2;
    const int gid = lane >> 2, tig = lane & 3;
    #pragma unroll
    for (int mt=0; mt<2; mt++)
        #pragma unroll
        for (int nt=0; nt<4; nt++) {
            int row = m0 + wm*32 + mt*16 + gid;
            int col = n0 + wn*32 + nt*8 + 2*tig;
            float bv0 = Wrb[col], bv1 = Wrb[col+1];
            y[(size_t)row*Hsz + col  ]     = tanhf(cacc[mt][nt][0] + bv0);
            y[(size_t)row*Hsz + col+1]     = tanhf(cacc[mt][nt][1] + bv1);
            y[(size_t)(row+8)*Hsz + col  ] = tanhf(cacc[mt][nt][2] + bv0);
            y[(size_t)(row+8)*Hsz + col+1] = tanhf(cacc[mt][nt][3] + bv1);
        }
}

// ---- phase B: fp16 persistent recurrence, rotated tiles + SMEM epilogue -------
#define NST 4
#define WROWW 516
#define STG_BASEW 20640
#define STGW 4608
#define RED_OFF (STG_BASEW + NST*STGW)
#define PP_OFF  (RED_OFF + 5248)
#define PC_OFF  (PP_OFF + 5120)
#define SMEM_WORDS (PC_OFF + 1024)
#define SMEM_BYTES (SMEM_WORDS*4)

__global__ void __launch_bounds__(512, 1)
lstm_persist(const float* __restrict__ Whi, const float* __restrict__ Whf,
             const float* __restrict__ Whg, const float* __restrict__ Who,
             const float* __restrict__ Whd)
{
    extern __shared__ float sm[];
    unsigned* smw = reinterpret_cast<unsigned*>(sm);
    __half*   smh = reinterpret_cast<__half*>(sm);
    const unsigned smb = (unsigned)__cvta_generic_to_shared(sm);
    const int cb  = blockIdx.x;
    const int h0  = cb * 8;
    const int rot = cb >> 3;
    const int tid = threadIdx.x, lane = tid & 31, wid = tid >> 5;
    const int gid = lane >> 2, tig = lane & 3;
    const int wm  = wid & 3;
    const int kq  = wid >> 2;

    for (int i = tid; i < 40*1024; i += 512) {
        int n = i >> 10, k = i & 1023;
        int g = n >> 3, r = n & 7;
        const float* Wg = g==0?Whi : g==1?Whf : g==2?Whg : g==3?Who : Whd;
        smh[n*1032 + k] = __float2half_rn(Wg[(size_t)(h0+r)*Hsz + k]);
    }
    __syncthreads();

    const int c0r  = (tid*2) >> 3;
    const int c0o  = (tid*2) & 7;

    for (int t = 0; t < Tsz; t++) {
        const __half* __restrict__ hprev = g_h2[t & 1];

        // ---- epilogue-operand prefetch: g_P slab + c -> SMEM (group 0) ----
        // 1536 16B chunks: 1280 for g_P (5 gates x 128 b x 8 floats), 256 for c.
        for (int ch = tid; ch < 1536; ch += 512) {
            if (ch < 1280) {
                int pair = ch >> 1, half = ch & 1;
                int g = pair >> 7, b = pair & 127;
                const float* src = &g_P[0][0][0][0] +
                    (((size_t)g*Tsz + t)*Bsz + b)*Hsz + h0 + half*4;
                cpasync16(smb + (PP_OFF + pair*8 + half*4)*4, src);
            } else {
                int q = ch - 1280;
                int b = q >> 1, half = q & 1;
                cpasync16(smb + (PC_OFF + b*8 + half*4)*4,
                          g_c + (size_t)b*Hsz + h0 + half*4);
            }
        }
        CP_COMMIT();

        // ---- prologue: poll own-rotation tiles, then prefetch 3 stages ----
        if (wid == 0 && lane < 8) {
            #pragma unroll
            for (int jp = 0; jp < 3; jp++) {
                const int pt = (rot + jp) & 15;
                const int* fp = &g_flag[(pt*8 + lane)*8];
                while (ld_acq(fp) < t) {}
            }
        }
        __syncthreads();
        #pragma unroll
        for (int jp = 0; jp < 3; jp++) {
            const int pt = (rot + jp) & 15;
            unsigned dst = smb + (STG_BASEW + jp*STGW)*4 + c0r*144 + c0o*16;
            const __half* src = hprev + (size_t)c0r*Hsz + pt*64 + c0o*8;
            cpasync16(dst,      src);
            cpasync16(dst + 16, src + 8);
            CP_COMMIT();
        }

        float cacc[2][5][4];
        #pragma unroll
        for (int mt=0; mt<2; mt++)
            #pragma unroll
            for (int g=0; g<5; g++)
                { cacc[mt][g][0]=0.f; cacc[mt][g][1]=0.f; cacc[mt][g][2]=0.f; cacc[mt][g][3]=0.f; }

        for (int j = 0; j < 16; j++) {
            asm volatile("cp.async.wait_group 2;" ::: "memory");
            const int jj = j + 3;
            if (jj < 16 && wid == 0 && lane < 8) {
                const int pt = (rot + jj) & 15;
                const int* fp = &g_flag[(pt*8 + lane)*8];
                while (ld_acq(fp) < t) {}
            }
            __syncthreads();
            if (jj < 16) {
                const int pt = (rot + jj) & 15;
                unsigned dst = smb + (STG_BASEW + (jj & 3)*STGW)*4 + c0r*144 + c0o*16;
                const __half* src = hprev + (size_t)c0r*Hsz + pt*64 + c0o*8;
                cpasync16(dst,      src);
                cpasync16(dst + 16, src + 8);
            }
            CP_COMMIT();

            const unsigned stw = STG_BASEW + (j & 3)*STGW;
            const int ptile = (rot + j) & 15;
            unsigned a[2][4];
            #pragma unroll
            for (int mt=0; mt<2; mt++) {
                unsigned base = stw + (unsigned)(wm*32 + mt*16 + gid)*36 + kq*8 + tig;
                a[mt][0] = smw[base];
                a[mt][1] = smw[base + 8*36];
                a[mt][2] = smw[base + 4];
                a[mt][3] = smw[base + 8*36 + 4];
            }
            const unsigned wb0 = (unsigned)ptile*32 + kq*8 + tig;
            #pragma unroll
            for (int g=0; g<5; g++) {
                unsigned wb = (unsigned)(g*8 + gid)*WROWW + wb0;
                unsigned b0 = smw[wb], b1 = smw[wb + 4];
                mma16(cacc[0][g], a[0], b0, b1);
                mma16(cacc[1][g], a[1], b0, b1);
            }
        }
        __syncthreads();

        // ---- 3-round tree reduction over k-quarters ----
        float* red = &sm[RED_OFF + wm*(32*41) + lane*41];
        if (kq == 1) {
            #pragma unroll
            for (int mt=0; mt<2; mt++) for (int g=0; g<5; g++) for (int r=0; r<4; r++)
                red[mt*20 + g*4 + r] = cacc[mt][g][r];
        }
        __syncthreads();
        if (kq == 0) {
            #pragma unroll
            for (int mt=0; mt<2; mt++) for (int g=0; g<5; g++) for (int r=0; r<4; r++)
                cacc[mt][g][r] += red[mt*20 + g*4 + r];
        }
        __syncthreads();
        if (kq == 3) {
            #pragma unroll
            for (int mt=0; mt<2; mt++) for (int g=0; g<5; g++) for (int r=0; r<4; r++)
                red[mt*20 + g*4 + r] = cacc[mt][g][r];
        }
        __syncthreads();
        if (kq == 2) {
            #pragma unroll
            for (int mt=0; mt<2; mt++) for (int g=0; g<5; g++) for (int r=0; r<4; r++)
                cacc[mt][g][r] += red[mt*20 + g*4 + r];
        }
        __syncthreads();
        if (kq == 2) {
            #pragma unroll
            for (int mt=0; mt<2; mt++) for (int g=0; g<5; g++) for (int r=0; r<4; r++)
                red[mt*20 + g*4 + r] = cacc[mt][g][r];
        }
        __syncthreads();

        if (kq == 0) {
            __half* __restrict__ hnext = g_h2[(t+1) & 1];
            #pragma unroll
            for (int mt=0; mt<2; mt++)
                #pragma unroll
                for (int rp=0; rp<2; rp++) {
                    int b = wm*32 + mt*16 + gid + rp*8;
                    int h = h0 + 2*tig;
                    float cn2[2], hn2[2];
                    const float* pc = &sm[PC_OFF + b*8 + 2*tig];
                    #pragma unroll
                    for (int c = 0; c < 2; c++) {
                        int r = rp*2 + c;
                        float pi = cacc[mt][0][r] + red[mt*20 + 0*4 + r] + sm[PP_OFF + (0*128 + b)*8 + 2*tig + c];
                        float pf = cacc[mt][1][r] + red[mt*20 + 1*4 + r] + sm[PP_OFF + (1*128 + b)*8 + 2*tig + c];
                        float pg = cacc[mt][2][r] + red[mt*20 + 2*4 + r] + sm[PP_OFF + (2*128 + b)*8 + 2*tig + c];
                        float po = cacc[mt][3][r] + red[mt*20 + 3*4 + r] + sm[PP_OFF + (3*128 + b)*8 + 2*tig + c];
                        float pd = cacc[mt][4][r] + red[mt*20 + 4*4 + r] + sm[PP_OFF + (4*128 + b)*8 + 2*tig + c];
                        float iv = sig_fast(pi), fv = sig_fast(pf), gv = tanh_fast(pg);
                        float ov = sig_fast(po), dv = sig_fast(pd);
                        cn2[c] = fv*pc[c] + iv*gv + dv;
                        hn2[c] = ov * tanh_fast(cn2[c]);
                    }
                    *reinterpret_cast<float2*>(&g_c[(size_t)b*Hsz + h]) = make_float2(cn2[0], cn2[1]);
                    __half2 hh = __floats2half2_rn(hn2[0], hn2[1]);
                    *reinterpret_cast<__half2*>(&hnext[(size_t)b*Hsz + h]) = hh;
                    *reinterpret_cast<__half2*>(&g_HS16[((size_t)b*Tsz + t)*Hsz + h]) = hh;
                    if (t == Tsz - 1)
                        *reinterpret_cast<float2*>(&g_hlast[(size_t)b*Hsz + h]) = make_float2(hn2[0], hn2[1]);
                }
        }
        __syncthreads();
        if (tid == 0) st_release_flag(&g_flag[cb*8], t + 1);
    }
}

// ---- init / tail -------------------------------------------------------------
__global__ void init_state(const float* __restrict__ hidden, const float* __restrict__ cell){
    int i = blockIdx.x * 256 + threadIdx.x;
    g_h2[0][i] = __float2half_rn(hidden[i]);
    g_c[i]     = cell[i];
    if (blockIdx.x == 0 && threadIdx.x < Bsz) g_flag[threadIdx.x * 8] = 0;
}
__global__ void write_tail(float* __restrict__ out){
    int i = blockIdx.x * 256 + threadIdx.x;
    out[(size_t)Bsz*Tsz*Hsz + i]           = g_hlast[i];
    out[(size_t)Bsz*Tsz*Hsz + Bsz*Hsz + i] = g_c[i];
}

extern "C" void kernel_launch(void* const* d_in, const int* in_sizes, int n_in,
                              void* d_out, int out_size)
{
    const float *x, *xd, *hidden, *cell;
    const float *Wii,*Wif,*Wig,*Wio,*Wid,*Wro,*Whi,*Whf,*Whg,*Who,*Whd;
    const float *bi,*bf,*bg,*bo,*bd,*Wrb;

    x      = (const float*)d_in[0];
    xd     = (const float*)d_in[1];
    hidden = (const float*)d_in[2];
    cell   = (const float*)d_in[3];

    if (in_sizes[5] == Hsz*Isz) {
        Wii=(const float*)d_in[4];  Wif=(const float*)d_in[5];  Wig=(const float*)d_in[6];
        Wio=(const float*)d_in[7];  Wid=(const float*)d_in[8];  Wro=(const float*)d_in[9];
        Whi=(const float*)d_in[10]; Whf=(const float*)d_in[11]; Whg=(const float*)d_in[12];
        Who=(const float*)d_in[13]; Whd=(const float*)d_in[14];
        bi=(const float*)d_in[15];  bf=(const float*)d_in[16];  bg=(const float*)d_in[17];
        bo=(const float*)d_in[18];  bd=(const float*)d_in[19];  Wrb=(const float*)d_in[20];
    } else {
        Wii=(const float*)d_in[4];  Whi=(const float*)d_in[5];  bi =(const float*)d_in[6];
        Wif=(const float*)d_in[7];  Whf=(const float*)d_in[8];  bf =(const float*)d_in[9];
        Wig=(const float*)d_in[10]; Whg=(const float*)d_in[11]; bg =(const float*)d_in[12];
        Wio=(const float*)d_in[13]; Who=(const float*)d_in[14]; bo =(const float*)d_in[15];
        Wid=(const float*)d_in[16]; Whd=(const float*)d_in[17]; bd =(const float*)d_in[18];
        Wro=(const float*)d_in[19]; Wrb=(const float*)d_in[20];
    }

    float* out = (float*)d_out;

    cudaFuncSetAttribute(lstm_persist, cudaFuncAttributeMaxDynamicSharedMemorySize, SMEM_BYTES);

    init_state<<<(Bsz*Hsz)/256, 256>>>(hidden, cell);

    cvt_all<<<(Mpre*Isz)/256, 256>>>(x, xd, Wii, Wif, Wig, Wio, Wid, Wro, Who);

    gemm_pre16<<<dim3(Hsz/BN, Mpre/BM, 5), 256>>>(bi, bf, bg, bo, bd);

    lstm_persist<<<Bsz, 512, SMEM_BYTES>>>(Whi, Whf, Whg, Who, Whd);

    gemm_out16<<<dim3(Hsz/BN, Mpre/BM), 256>>>(Wrb, out);

    write_tail<<<(Bsz*Hsz)/256, 256>>>(out);
}

// round 15
// speedup vs baseline: 1.2212x; 1.2212x over previous
#include <cuda_runtime.h>
#include <cuda_fp16.h>
#include <cstdint>
#include <math.h>

#define Bsz 128
#define Tsz 256
#define Isz 512
#define Hsz 1024
#define Mpre (Bsz*Tsz)
#define BM 128
#define BN 64

__device__ float  g_P[5][Tsz][Bsz][Hsz];
__device__ __half g_HS16[(size_t)Mpre*Hsz];
__device__ float  g_hlast[Bsz*Hsz];
__device__ __half g_h2[2][Bsz*Hsz];
__device__ float  g_c[Bsz*Hsz];
__device__ int    g_flag[Bsz*8];
__device__ __half g_x16[(size_t)Mpre*Isz];
__device__ __half g_xd16[(size_t)Mpre*Isz];
__device__ __half g_w16[5][Hsz*Isz];
__device__ __half g_wro16[Hsz*Isz];
__device__ __half g_who16[(size_t)Hsz*Hsz];

__device__ __forceinline__ void mma16(float c[4], const unsigned a[4], unsigned b0, unsigned b1){
    asm volatile("mma.sync.aligned.m16n8k16.row.col.f32.f16.f16.f32 "
        "{%0,%1,%2,%3},{%4,%5,%6,%7},{%8,%9},{%0,%1,%2,%3};"
        : "+f"(c[0]),"+f"(c[1]),"+f"(c[2]),"+f"(c[3])
        : "r"(a[0]),"r"(a[1]),"r"(a[2]),"r"(a[3]),"r"(b0),"r"(b1));
}
__device__ __forceinline__ float tanh_fast(float x){
    float r; asm("tanh.approx.f32 %0, %1;" : "=f"(r) : "f"(x)); return r;
}
__device__ __forceinline__ float sig_fast(float x){
    return 0.5f + 0.5f * tanh_fast(0.5f * x);
}
__device__ __forceinline__ int ld_acq(const int* p){
    int v; asm volatile("ld.global.acquire.gpu.b32 %0, [%1];" : "=r"(v) : "l"(p) : "memory");
    return v;
}
__device__ __forceinline__ void st_release_flag(int* p, int v){
    int old;
    asm volatile("atom.release.gpu.global.exch.b32 %0, [%1], %2;"
                 : "=r"(old) : "l"(p), "r"(v) : "memory");
}
__device__ __forceinline__ void cpasync16(unsigned dst, const void* src){
    asm volatile("cp.async.cg.shared.global [%0], [%1], 16;" :: "r"(dst), "l"(src));
}
#define CP_COMMIT() asm volatile("cp.async.commit_group;" ::: "memory")

// ---- one-shot fp32 -> fp16 conversion of GEMM operands ----------------------
__global__ void cvt_all(const float* __restrict__ x, const float* __restrict__ xd,
    const float* __restrict__ Wii, const float* __restrict__ Wif,
    const float* __restrict__ Wig, const float* __restrict__ Wio,
    const float* __restrict__ Wid, const float* __restrict__ Wro,
    const float* __restrict__ Who)
{
    size_t i = (size_t)blockIdx.x*256 + threadIdx.x;
    if (i < (size_t)Mpre*Isz) {
        g_x16[i]  = __float2half_rn(x[i]);
        g_xd16[i] = __float2half_rn(xd[i]);
    }
    if (i < (size_t)Hsz*Isz) {
        g_w16[0][i] = __float2half_rn(Wii[i]);
        g_w16[1][i] = __float2half_rn(Wif[i]);
        g_w16[2][i] = __float2half_rn(Wig[i]);
        g_w16[3][i] = __float2half_rn(Wio[i]);
        g_w16[4][i] = __float2half_rn(Wid[i]);
        g_wro16[i]  = __float2half_rn(Wro[i]);
    }
    if (i < (size_t)Hsz*Hsz) g_who16[i] = __float2half_rn(Who[i]);
}

// ---- fp16 GEMM panel (unchanged from R12) -----------------------------------
__device__ __forceinline__ void gemm16_panel(
    const __half* __restrict__ A, int lda,
    const __half* __restrict__ B, int ldb,
    int K, int tid, unsigned smb, const unsigned* __restrict__ smw,
    float (&cacc)[2][4][4])
{
    const int lane = tid & 31, wid = tid >> 5;
    const int wm = wid & 3, wn = wid >> 2;
    const int gid = lane >> 2, tig = lane & 3;
    const int ra = tid >> 1, qa = (tid & 1) * 2;
    const int rb = tid >> 2, qb = tid & 3;
    const int nIter = K >> 5;

    {
        unsigned dA = smb + (unsigned)(ra*40 + qa*8)*2;
        const __half* sa = A + (size_t)ra*lda + qa*8;
        cpasync16(dA, sa); cpasync16(dA + 16, sa + 8);
        unsigned dB = smb + 10240u + (unsigned)(rb*40 + qb*8)*2;
        cpasync16(dB, B + (size_t)rb*ldb + qb*8);
        CP_COMMIT();
    }
    for (int it = 0; it < nIter; it++) {
        if (it + 1 < nIter) {
            const int k0 = (it + 1) << 5;
            const unsigned bo = (unsigned)((it + 1) & 1) * 15360u;
            unsigned dA = smb + bo + (unsigned)(ra*40 + qa*8)*2;
            const __half* sa = A + (size_t)ra*lda + k0 + qa*8;
            cpasync16(dA, sa); cpasync16(dA + 16, sa + 8);
            unsigned dB = smb + bo + 10240u + (unsigned)(rb*40 + qb*8)*2;
            cpasync16(dB, B + (size_t)rb*ldb + k0 + qb*8);
        }
        CP_COMMIT();
        asm volatile("cp.async.wait_group 1;" ::: "memory");
        __syncthreads();

        const unsigned* wA = smw + (it & 1)*3840;
        const unsigned* wB = wA + 2560;
        #pragma unroll
        for (int kk = 0; kk < 2; kk++) {
            unsigned a[2][4];
            #pragma unroll
            for (int mt = 0; mt < 2; mt++) {
                int base = (wm*32 + mt*16 + gid)*20 + kk*8 + tig;
                a[mt][0] = wA[base];       a[mt][1] = wA[base + 160];
                a[mt][2] = wA[base + 4];   a[mt][3] = wA[base + 164];
            }
            #pragma unroll
            for (int nt = 0; nt < 4; nt++) {
                int wb = (wn*32 + nt*8 + gid)*20 + kk*8 + tig;
                unsigned b0 = wB[wb], b1 = wB[wb + 4];
                mma16(cacc[0][nt], a[0], b0, b1);
                mma16(cacc[1][nt], a[1], b0, b1);
            }
        }
        __syncthreads();
    }
}

// ---- phase A ------------------------------------------------------------------
__global__ __launch_bounds__(256)
void gemm_pre16(const float* __restrict__ b0, const float* __restrict__ b1,
                const float* __restrict__ b2, const float* __restrict__ b3,
                const float* __restrict__ b4)
{
    __shared__ __half st[15360];
    const unsigned smb = (unsigned)__cvta_generic_to_shared(st);
    const unsigned* smw = reinterpret_cast<const unsigned*>(st);
    const int gate = blockIdx.z;
    const int m0 = blockIdx.y * BM;
    const int n0 = blockIdx.x * BN;
    const int tid = threadIdx.x;
    const __half* A  = ((gate == 4) ? g_xd16 : g_x16) + (size_t)m0*Isz;
    const __half* Bp = g_w16[gate] + (size_t)n0*Isz;
    const float* bias = gate==0?b0 : gate==1?b1 : gate==2?b2 : gate==3?b3 : b4;

    float cacc[2][4][4];
    #pragma unroll
    for (int i=0;i<2;i++) for (int j=0;j<4;j++) for (int k=0;k<4;k++) cacc[i][j][k]=0.f;

    gemm16_panel(A, Isz, Bp, Isz, Isz, tid, smb, smw, cacc);

    const int lane = tid & 31, wid = tid >> 5;
    const int wm = wid & 3, wn = wid >> 2;
    const int gid = lane >> 2, tig = lane & 3;
    #pragma unroll
    for (int mt=0; mt<2; mt++)
        #pragma unroll
        for (int nt=0; nt<4; nt++) {
            int row = m0 + wm*32 + mt*16 + gid;
            int b = row >> 8, tt = row & 255;
            int col = n0 + wn*32 + nt*8 + 2*tig;
            float bv0 = bias[col], bv1 = bias[col+1];
            g_P[gate][tt  ][b][col  ] = cacc[mt][nt][0] + bv0;
            g_P[gate][tt  ][b][col+1] = cacc[mt][nt][1] + bv1;
            g_P[gate][tt+8][b][col  ] = cacc[mt][nt][2] + bv0;
            g_P[gate][tt+8][b][col+1] = cacc[mt][nt][3] + bv1;
        }
}

// ---- phase C ------------------------------------------------------------------
__global__ __launch_bounds__(256)
void gemm_out16(const float* __restrict__ Wrb, float* __restrict__ y)
{
    __shared__ __half st[15360];
    const unsigned smb = (unsigned)__cvta_generic_to_shared(st);
    const unsigned* smw = reinterpret_cast<const unsigned*>(st);
    const int m0 = blockIdx.y * BM;
    const int n0 = blockIdx.x * BN;
    const int tid = threadIdx.x;

    float cacc[2][4][4];
    #pragma unroll
    for (int i=0;i<2;i++) for (int j=0;j<4;j++) for (int k=0;k<4;k++) cacc[i][j][k]=0.f;

    gemm16_panel(g_x16  + (size_t)m0*Isz, Isz, g_wro16 + (size_t)n0*Isz, Isz, Isz, tid, smb, smw, cacc);
    gemm16_panel(g_HS16 + (size_t)m0*Hsz, Hsz, g_who16 + (size_t)n0*Hsz, Hsz, Hsz, tid, smb, smw, cacc);

    const int lane = tid & 31, wid = tid >> 5;
    const int wm = wid & 3, wn = wid >> 2;
    const int gid = lane >> 2, tig = lane & 3;
    #pragma unroll
    for (int mt=0; mt<2; mt++)
        #pragma unroll
        for (int nt=0; nt<4; nt++) {
            int row = m0 + wm*32 + mt*16 + gid;
            int col = n0 + wn*32 + nt*8 + 2*tig;
            float bv0 = Wrb[col], bv1 = Wrb[col+1];
            y[(size_t)row*Hsz + col  ]     = tanhf(cacc[mt][nt][0] + bv0);
            y[(size_t)row*Hsz + col+1]     = tanhf(cacc[mt][nt][1] + bv1);
            y[(size_t)(row+8)*Hsz + col  ] = tanhf(cacc[mt][nt][2] + bv0);
            y[(size_t)(row+8)*Hsz + col+1] = tanhf(cacc[mt][nt][3] + bv1);
        }
}

// ---- phase B: fp16 persistent recurrence, pair-granularity 6-stage pipeline ---
#define NST 6
#define WROWW 516
#define STG_BASEW 20640                    /* 40*516 words                */
#define STGW 4608                          /* 128*36 words per stage      */
#define SMEM_WORDS (STG_BASEW + NST*STGW)  /* 48288 words = 193,152 B     */
#define SMEM_BYTES (SMEM_WORDS*4)
/* reduction buffers reuse the stage area after the k-loop */

__global__ void __launch_bounds__(512, 1)
lstm_persist(const float* __restrict__ Whi, const float* __restrict__ Whf,
             const float* __restrict__ Whg, const float* __restrict__ Who,
             const float* __restrict__ Whd)
{
    extern __shared__ float sm[];
    unsigned* smw = reinterpret_cast<unsigned*>(sm);
    __half*   smh = reinterpret_cast<__half*>(sm);
    const unsigned smb = (unsigned)__cvta_generic_to_shared(sm);
    const int cb  = blockIdx.x;
    const int h0  = cb * 8;
    const int tid = threadIdx.x, lane = tid & 31, wid = tid >> 5;
    const int gid = lane >> 2, tig = lane & 3;
    const int wm  = wid & 3;
    const int kq  = wid >> 2;

    for (int i = tid; i < 40*1024; i += 512) {
        int n = i >> 10, k = i & 1023;
        int g = n >> 3, r = n & 7;
        const float* Wg = g==0?Whi : g==1?Whf : g==2?Whg : g==3?Who : Whd;
        smh[n*1032 + k] = __float2half_rn(Wg[(size_t)(h0+r)*Hsz + k]);
    }
    __syncthreads();

    const int c0r  = (tid*2) >> 3;
    const int c0o  = (tid*2) & 7;

    for (int t = 0; t < Tsz; t++) {
        const __half* __restrict__ hprev = g_h2[t & 1];

        // ---- prologue: poll group 0 (flags 0..31 = tiles 0..3), prefetch pairs 0,1
        if (wid == 0) { const int* fp = &g_flag[lane*8]; while (ld_acq(fp) < t) {} }
        __syncthreads();
        #pragma unroll
        for (int pp = 0; pp < 2; pp++) {
            #pragma unroll
            for (int jt = 0; jt < 2; jt++) {
                const int j = 2*pp + jt;
                unsigned dst = smb + (STG_BASEW + j*STGW)*4 + c0r*144 + c0o*16;
                const __half* src = hprev + (size_t)c0r*Hsz + j*64 + c0o*8;
                cpasync16(dst,      src);
                cpasync16(dst + 16, src + 8);
            }
            CP_COMMIT();
        }

        float cacc[2][5][4];
        #pragma unroll
        for (int mt=0; mt<2; mt++)
            #pragma unroll
            for (int g=0; g<5; g++)
                { cacc[mt][g][0]=0.f; cacc[mt][g][1]=0.f; cacc[mt][g][2]=0.f; cacc[mt][g][3]=0.f; }

        for (int p = 0; p < 8; p++) {
            asm volatile("cp.async.wait_group 1;" ::: "memory");
            const int jn = 2*p + 4;                     // first tile of pair p+2
            if (((p & 1) == 0) && jn < 16 && wid == 0) { // poll tiles jn..jn+3
                const int* fp = &g_flag[(((p + 2) >> 1)*32 + lane)*8];
                while (ld_acq(fp) < t) {}
            }
            __syncthreads();
            if (jn < 16) {
                #pragma unroll
                for (int jt = 0; jt < 2; jt++) {
                    const int j = jn + jt;
                    const int s = j % NST;
                    unsigned dst = smb + (STG_BASEW + s*STGW)*4 + c0r*144 + c0o*16;
                    const __half* src = hprev + (size_t)c0r*Hsz + j*64 + c0o*8;
                    cpasync16(dst,      src);
                    cpasync16(dst + 16, src + 8);
                }
            }
            CP_COMMIT();

            #pragma unroll
            for (int jt = 0; jt < 2; jt++) {
                const int j = 2*p + jt;
                const int s = j % NST;
                const unsigned stw = STG_BASEW + (unsigned)s*STGW;
                unsigned a[2][4];
                #pragma unroll
                for (int mt=0; mt<2; mt++) {
                    unsigned base = stw + (unsigned)(wm*32 + mt*16 + gid)*36 + kq*8 + tig;
                    a[mt][0] = smw[base];
                    a[mt][1] = smw[base + 288];
                    a[mt][2] = smw[base + 4];
                    a[mt][3] = smw[base + 292];
                }
                const unsigned wb0 = (unsigned)j*32 + kq*8 + tig;
                #pragma unroll
                for (int g=0; g<5; g++) {
                    unsigned wb = (unsigned)(g*8 + gid)*WROWW + wb0;
                    unsigned b0 = smw[wb], b1 = smw[wb + 4];
                    mma16(cacc[0][g], a[0], b0, b1);
                    mma16(cacc[1][g], a[1], b0, b1);
                }
            }
        }
        __syncthreads();   // k-loop done; stages become reduction scratch

        // ---- epilogue operand prefetch (registers; overlaps reduction) ----
        float2 pre[2][2][5], cpre[2][2];
        if (kq == 0) {
            #pragma unroll
            for (int mt=0; mt<2; mt++)
                #pragma unroll
                for (int rp=0; rp<2; rp++) {
                    int b = wm*32 + mt*16 + gid + rp*8;
                    int h = h0 + 2*tig;
                    #pragma unroll
                    for (int g=0; g<5; g++)
                        pre[mt][rp][g] = *reinterpret_cast<const float2*>(&g_P[g][t][b][h]);
                    cpre[mt][rp] = *reinterpret_cast<const float2*>(&g_c[(size_t)b*Hsz + h]);
                }
        }

        // ---- single-round reduction over k-quarters ----
        if (kq >= 1) {
            float* red = &sm[STG_BASEW + ((kq - 1)*4 + wm)*1312 + lane*41];
            #pragma unroll
            for (int mt=0; mt<2; mt++) for (int g=0; g<5; g++) for (int r=0; r<4; r++)
                red[mt*20 + g*4 + r] = cacc[mt][g][r];
        }
        __syncthreads();
        unsigned hhsave[2][2];
        if (kq == 0) {
            #pragma unroll
            for (int q = 0; q < 3; q++) {
                const float* red = &sm[STG_BASEW + (q*4 + wm)*1312 + lane*41];
                #pragma unroll
                for (int mt=0; mt<2; mt++) for (int g=0; g<5; g++) for (int r=0; r<4; r++)
                    cacc[mt][g][r] += red[mt*20 + g*4 + r];
            }
            __half* __restrict__ hnext = g_h2[(t+1) & 1];
            #pragma unroll
            for (int mt=0; mt<2; mt++)
                #pragma unroll
                for (int rp=0; rp<2; rp++) {
                    int b = wm*32 + mt*16 + gid + rp*8;
                    int h = h0 + 2*tig;
                    float cn2[2], hn2[2];
                    #pragma unroll
                    for (int c = 0; c < 2; c++) {
                        int r = rp*2 + c;
                        float pi = cacc[mt][0][r] + ((c==0)?pre[mt][rp][0].x:pre[mt][rp][0].y);
                        float pf = cacc[mt][1][r] + ((c==0)?pre[mt][rp][1].x:pre[mt][rp][1].y);
                        float pg = cacc[mt][2][r] + ((c==0)?pre[mt][rp][2].x:pre[mt][rp][2].y);
                        float po = cacc[mt][3][r] + ((c==0)?pre[mt][rp][3].x:pre[mt][rp][3].y);
                        float pd = cacc[mt][4][r] + ((c==0)?pre[mt][rp][4].x:pre[mt][rp][4].y);
                        float iv = sig_fast(pi), fv = sig_fast(pf), gv = tanh_fast(pg);
                        float ov = sig_fast(po), dv = sig_fast(pd);
                        float cp = (c==0) ? cpre[mt][rp].x : cpre[mt][rp].y;
                        cn2[c] = fv*cp + iv*gv + dv;
                        hn2[c] = ov * tanh_fast(cn2[c]);
                    }
                    *reinterpret_cast<float2*>(&g_c[(size_t)b*Hsz + h]) = make_float2(cn2[0], cn2[1]);
                    __half2 hh = __floats2half2_rn(hn2[0], hn2[1]);
                    *reinterpret_cast<__half2*>(&hnext[(size_t)b*Hsz + h]) = hh;
                    hhsave[mt][rp] = *reinterpret_cast<unsigned*>(&hh);
                    if (t == Tsz - 1)
                        *reinterpret_cast<float2*>(&g_hlast[(size_t)b*Hsz + h]) = make_float2(hn2[0], hn2[1]);
                }
        }
        __syncthreads();
        if (tid == 0) st_release_flag(&g_flag[cb*8], t + 1);

        // g_HS16 stores off the cross-CTA handoff path
        if (kq == 0) {
            #pragma unroll
            for (int mt=0; mt<2; mt++)
                #pragma unroll
                for (int rp=0; rp<2; rp++) {
                    int b = wm*32 + mt*16 + gid + rp*8;
                    int h = h0 + 2*tig;
                    *reinterpret_cast<unsigned*>(&g_HS16[((size_t)b*Tsz + t)*Hsz + h]) = hhsave[mt][rp];
                }
        }
    }
}

// ---- init / tail -------------------------------------------------------------
__global__ void init_state(const float* __restrict__ hidden, const float* __restrict__ cell){
    int i = blockIdx.x * 256 + threadIdx.x;
    g_h2[0][i] = __float2half_rn(hidden[i]);
    g_c[i]     = cell[i];
    if (blockIdx.x == 0 && threadIdx.x < Bsz) g_flag[threadIdx.x * 8] = 0;
}
__global__ void write_tail(float* __restrict__ out){
    int i = blockIdx.x * 256 + threadIdx.x;
    out[(size_t)Bsz*Tsz*Hsz + i]           = g_hlast[i];
    out[(size_t)Bsz*Tsz*Hsz + Bsz*Hsz + i] = g_c[i];
}

extern "C" void kernel_launch(void* const* d_in, const int* in_sizes, int n_in,
                              void* d_out, int out_size)
{
    const float *x, *xd, *hidden, *cell;
    const float *Wii,*Wif,*Wig,*Wio,*Wid,*Wro,*Whi,*Whf,*Whg,*Who,*Whd;
    const float *bi,*bf,*bg,*bo,*bd,*Wrb;

    x      = (const float*)d_in[0];
    xd     = (const float*)d_in[1];
    hidden = (const float*)d_in[2];
    cell   = (const float*)d_in[3];

    if (in_sizes[5] == Hsz*Isz) {
        Wii=(const float*)d_in[4];  Wif=(const float*)d_in[5];  Wig=(const float*)d_in[6];
        Wio=(const float*)d_in[7];  Wid=(const float*)d_in[8];  Wro=(const float*)d_in[9];
        Whi=(const float*)d_in[10]; Whf=(const float*)d_in[11]; Whg=(const float*)d_in[12];
        Who=(const float*)d_in[13]; Whd=(const float*)d_in[14];
        bi=(const float*)d_in[15];  bf=(const float*)d_in[16];  bg=(const float*)d_in[17];
        bo=(const float*)d_in[18];  bd=(const float*)d_in[19];  Wrb=(const float*)d_in[20];
    } else {
        Wii=(const float*)d_in[4];  Whi=(const float*)d_in[5];  bi =(const float*)d_in[6];
        Wif=(const float*)d_in[7];  Whf=(const float*)d_in[8];  bf =(const float*)d_in[9];
        Wig=(const float*)d_in[10]; Whg=(const float*)d_in[11]; bg =(const float*)d_in[12];
        Wio=(const float*)d_in[13]; Who=(const float*)d_in[14]; bo =(const float*)d_in[15];
        Wid=(const float*)d_in[16]; Whd=(const float*)d_in[17]; bd =(const float*)d_in[18];
        Wro=(const float*)d_in[19]; Wrb=(const float*)d_in[20];
    }

    float* out = (float*)d_out;

    cudaFuncSetAttribute(lstm_persist, cudaFuncAttributeMaxDynamicSharedMemorySize, SMEM_BYTES);

    init_state<<<(Bsz*Hsz)/256, 256>>>(hidden, cell);

    cvt_all<<<(Mpre*Isz)/256, 256>>>(x, xd, Wii, Wif, Wig, Wio, Wid, Wro, Who);

    gemm_pre16<<<dim3(Hsz/BN, Mpre/BM, 5), 256>>>(bi, bf, bg, bo, bd);

    lstm_persist<<<Bsz, 512, SMEM_BYTES>>>(Whi, Whf, Whg, Who, Whd);

    gemm_out16<<<dim3(Hsz/BN, Mpre/BM), 256>>>(Wrb, out);

    write_tail<<<(Bsz*Hsz)/256, 256>>>(out);
}